// round 5
// baseline (speedup 1.0000x reference)
#include <cuda_runtime.h>
#include <stdint.h>

#define BATCH 2048
#define EPS 1e-5f

// ---------------- static scratch ----------------
__device__ uint32_t           g_h1[BATCH * 784];        // stem out, 32 ch packed
__device__ unsigned long long g_h2[BATCH * 196];        // block1 out, 64 ch packed
__device__ uint32_t           g_h3u[BATCH * 49 * 2];    // block2 out, 2x u32 halves
__device__ uint32_t           g_w2p[64 * 12];           // sign(w2), stride 12 (uint4)
__device__ unsigned long long g_w3p[64 * 10];           // sign(w3), stride 10 (ulonglong2)
__device__ unsigned long long g_wfcp[256 * 49];         // sign(w_fc)
__device__ float4 g_bn1[32], g_bn2[64], g_bn3[64], g_bn4[256];  // (inv, mean, beta, 0)

// LOP3 helpers (guaranteed single-instruction 3-input boolean ops)
__device__ __forceinline__ uint32_t lop3_xm(uint32_t x, uint32_t w, uint32_t m) {
    uint32_t r;   // (x ^ w) & m
    asm("lop3.b32 %0, %1, %2, %3, 0x28;" : "=r"(r) : "r"(x), "r"(w), "r"(m));
    return r;
}
__device__ __forceinline__ uint32_t lop3_sum(uint32_t a, uint32_t b, uint32_t c) {
    uint32_t r;   // a ^ b ^ c
    asm("lop3.b32 %0, %1, %2, %3, 0x96;" : "=r"(r) : "r"(a), "r"(b), "r"(c));
    return r;
}
__device__ __forceinline__ uint32_t lop3_maj(uint32_t a, uint32_t b, uint32_t c) {
    uint32_t r;   // majority(a,b,c)
    asm("lop3.b32 %0, %1, %2, %3, 0xE8;" : "=r"(r) : "r"(a), "r"(b), "r"(c));
    return r;
}

// ---------------- packing + BN precompute ----------------
__global__ void pack_kernel(const float* __restrict__ w2, const float* __restrict__ w3,
                            const float* __restrict__ wfc,
                            const float* __restrict__ g1, const float* __restrict__ v1,
                            const float* __restrict__ m1, const float* __restrict__ b1,
                            const float* __restrict__ g2, const float* __restrict__ v2,
                            const float* __restrict__ m2, const float* __restrict__ b2,
                            const float* __restrict__ g3, const float* __restrict__ v3,
                            const float* __restrict__ m3, const float* __restrict__ b3,
                            const float* __restrict__ g4, const float* __restrict__ v4,
                            const float* __restrict__ m4, const float* __restrict__ b4) {
    int idx = blockIdx.x * 256 + threadIdx.x;
    if (idx < 768) {                                   // w2: [64,32,3,3] -> stride 12
        int o = idx / 12, t = idx % 12;
        uint32_t bits = 0;
        if (t < 9)
            for (int c = 0; c < 32; c++)
                bits |= (w2[o * 288 + c * 9 + t] >= 0.f ? 1u : 0u) << c;
        g_w2p[idx] = bits;
    } else if (idx < 1408) {                           // w3: [64,64,3,3] -> stride 10
        int j = idx - 768; int o = j / 10, t = j % 10;
        unsigned long long bits = 0;
        if (t < 9)
            for (int c = 0; c < 64; c++)
                bits |= (unsigned long long)(w3[o * 576 + c * 9 + t] >= 0.f) << c;
        g_w3p[j] = bits;
    } else if (idx < 13952) {                          // w_fc: [256,3136]
        int j = idx - 1408; int o = j / 49, p = j % 49;
        unsigned long long bits = 0;
        for (int c = 0; c < 64; c++)
            bits |= (unsigned long long)(wfc[o * 3136 + c * 49 + p] >= 0.f) << c;
        g_wfcp[j] = bits;
    } else if (idx < 13984) {
        int c = idx - 13952;
        g_bn1[c] = make_float4(g1[c] / sqrtf(v1[c] + EPS), m1[c], b1[c], 0.f);
    } else if (idx < 14048) {
        int c = idx - 13984;
        g_bn2[c] = make_float4(g2[c] / sqrtf(v2[c] + EPS), m2[c], b2[c], 0.f);
    } else if (idx < 14112) {
        int c = idx - 14048;
        g_bn3[c] = make_float4(g3[c] / sqrtf(v3[c] + EPS), m3[c], b3[c], 0.f);
    } else if (idx < 14368) {
        int c = idx - 14112;
        g_bn4[c] = make_float4(g4[c] / sqrtf(v4[c] + EPS), m4[c], b4[c], 0.f);
    }
}

// ---------------- stem: fp32 conv3x3(1->32) + BN + sign, 16 ch/thread ----------------
__global__ void __launch_bounds__(256) stem_kernel(const float* __restrict__ x,
                                                   const float* __restrict__ ws) {
    __shared__ float sw[288];
    __shared__ float4 sbn[32];
    int t = threadIdx.x;
    for (int i = t; i < 288; i += 256) sw[i] = ws[i];
    if (t < 32) sbn[t] = g_bn1[t];
    __syncthreads();

    int idx = blockIdx.x * 256 + t;
    int pix = idx >> 1, half = idx & 1;
    int b = pix / 784, p = pix % 784;
    int y = p / 28, xx = p % 28;
    const float* xb = x + b * 784;

    float win[9];
#pragma unroll
    for (int dy = 0; dy < 3; dy++)
#pragma unroll
        for (int dx = 0; dx < 3; dx++) {
            int yy = y + dy - 1, xc = xx + dx - 1;
            win[dy * 3 + dx] = (yy >= 0 && yy < 28 && xc >= 0 && xc < 28) ? xb[yy * 28 + xc] : 0.f;
        }

    int cb = half * 16;
    uint32_t bits = 0;
#pragma unroll
    for (int ci = 0; ci < 16; ci++) {
        int c = cb + ci;
        float s = 0.f;
#pragma unroll
        for (int k = 0; k < 9; k++) s += sw[c * 9 + k] * win[k];
        float4 bn = sbn[c];
        float v = (s - bn.y) * bn.x + bn.z;
        bits |= (v >= 0.f ? 1u : 0u) << ci;
    }
    ((uint16_t*)g_h1)[pix * 2 + half] = (uint16_t)bits;
}

// row-sum pair table: (window row, weight row, pool row)
__device__ __constant__ int c_pairI[6] = {0, 1, 2, 1, 2, 3};
__device__ __constant__ int c_pairW[6] = {0, 1, 2, 0, 1, 2};
__device__ __constant__ int c_pairP[6] = {0, 0, 0, 1, 1, 1};

// ---------------- block1: binary conv(32->64) + BN + pool + sign, CSA popc ----------------
__global__ void __launch_bounds__(256) conv2_kernel() {
    __shared__ __align__(16) uint32_t swt[768];
    __shared__ float4 sbn[64];
    int t = threadIdx.x;
    for (int i = t; i < 768; i += 256) swt[i] = g_w2p[i];
    if (t < 64) sbn[t] = g_bn2[t];
    __syncthreads();

    int idx = blockIdx.x * 256 + t;                 // 2048*196*2 threads
    int cell = idx >> 1, half = idx & 1;
    int b = cell / 196, p = cell % 196;
    int oy = p / 14, ox = p % 14;
    const uint32_t* h = g_h1 + b * 784;

    int rbase = 2 * oy - 1, cbase = 2 * ox - 1;
    bool rv0 = oy > 0, rv3 = oy < 13, cv0 = ox > 0, cv3 = ox < 13;

    uint32_t win[16], msk[16];
#pragma unroll
    for (int i = 0; i < 4; i++) {
        bool rok = (i == 0) ? rv0 : (i == 3 ? rv3 : true);
#pragma unroll
        for (int j = 0; j < 4; j++) {
            bool cok = (j == 0) ? cv0 : (j == 3 ? cv3 : true);
            bool v = rok && cok;
            msk[i * 4 + j] = v ? 0xFFFFFFFFu : 0u;
            win[i * 4 + j] = v ? h[(rbase + i) * 28 + (cbase + j)] : 0u;
        }
    }
    int vr0 = rv0 ? 3 : 2, vr1 = rv3 ? 3 : 2;
    int vc0 = cv0 ? 3 : 2, vc1 = cv3 ? 3 : 2;
    int base[4] = {32 * vr0 * vc0, 32 * vr0 * vc1, 32 * vr1 * vc0, 32 * vr1 * vc1};

    int cb = half * 32;
    uint32_t obits = 0;
#pragma unroll 1
    for (int ci = 0; ci < 32; ci++) {
        const uint4* wp = (const uint4*)(swt + (cb + ci) * 12);
        uint4 wa = wp[0], wb = wp[1], wc = wp[2];
        uint32_t w[9] = {wa.x, wa.y, wa.z, wa.w, wb.x, wb.y, wb.z, wb.w, wc.x};
        int ps[4] = {0, 0, 0, 0}, pc[4] = {0, 0, 0, 0};
#pragma unroll
        for (int pr = 0; pr < 6; pr++) {
            int i = c_pairI[pr], wr = c_pairW[pr], py = c_pairP[pr];
#pragma unroll
            for (int px = 0; px < 2; px++) {
                int k = i * 4 + px;
                uint32_t t0 = lop3_xm(win[k],     w[wr * 3],     msk[k]);
                uint32_t t1 = lop3_xm(win[k + 1], w[wr * 3 + 1], msk[k + 1]);
                uint32_t t2 = lop3_xm(win[k + 2], w[wr * 3 + 2], msk[k + 2]);
                uint32_t s  = lop3_sum(t0, t1, t2);
                uint32_t cr = lop3_maj(t0, t1, t2);
                ps[py * 2 + px] += __popc(s);
                pc[py * 2 + px] += __popc(cr);
            }
        }
        int d0 = base[0] - 2 * ps[0] - 4 * pc[0];
        int d1 = base[1] - 2 * ps[1] - 4 * pc[1];
        int d2 = base[2] - 2 * ps[2] - 4 * pc[2];
        int d3 = base[3] - 2 * ps[3] - 4 * pc[3];
        int dmax = max(max(d0, d1), max(d2, d3));
        int dmin = min(min(d0, d1), min(d2, d3));
        float4 bn = sbn[cb + ci];
        int ds = (bn.x >= 0.f) ? dmax : dmin;       // BN monotone in dot -> exact
        float val = ((float)ds - bn.y) * bn.x + bn.z;
        obits |= (uint32_t)(val >= 0.f) << ci;
    }
    ((uint32_t*)g_h2)[cell * 2 + half] = obits;
}

// ---------------- block2: binary conv(64->64) + BN + pool + sign, CSA popc ----------------
__global__ void __launch_bounds__(256) conv3_kernel() {
    __shared__ __align__(16) unsigned long long swt[640];
    __shared__ float4 sbn[64];
    int t = threadIdx.x;
    for (int i = t; i < 640; i += 256) swt[i] = g_w3p[i];
    if (t < 64) sbn[t] = g_bn3[t];
    __syncthreads();

    int idx = blockIdx.x * 256 + t;                 // 2048*49*2 threads
    int cell = idx >> 1, half = idx & 1;
    int b = cell / 49, p = cell % 49;
    int oy = p / 7, ox = p % 7;
    const unsigned long long* h = g_h2 + b * 196;

    int rbase = 2 * oy - 1, cbase = 2 * ox - 1;
    bool rv0 = oy > 0, rv3 = oy < 6, cv0 = ox > 0, cv3 = ox < 6;

    uint32_t wl[16], wh[16], msk[16];
#pragma unroll
    for (int i = 0; i < 4; i++) {
        bool rok = (i == 0) ? rv0 : (i == 3 ? rv3 : true);
#pragma unroll
        for (int j = 0; j < 4; j++) {
            bool cok = (j == 0) ? cv0 : (j == 3 ? cv3 : true);
            bool v = rok && cok;
            msk[i * 4 + j] = v ? 0xFFFFFFFFu : 0u;
            unsigned long long ww = v ? h[(rbase + i) * 14 + (cbase + j)] : 0ull;
            wl[i * 4 + j] = (uint32_t)ww;
            wh[i * 4 + j] = (uint32_t)(ww >> 32);
        }
    }
    int vr0 = rv0 ? 3 : 2, vr1 = rv3 ? 3 : 2;
    int vc0 = cv0 ? 3 : 2, vc1 = cv3 ? 3 : 2;
    int base[4] = {64 * vr0 * vc0, 64 * vr0 * vc1, 64 * vr1 * vc0, 64 * vr1 * vc1};

    int cb = half * 32;
    uint32_t obits = 0;
#pragma unroll 1
    for (int ci = 0; ci < 32; ci++) {
        const ulonglong2* wp = (const ulonglong2*)(swt + (cb + ci) * 10);
        ulonglong2 p0 = wp[0], p1 = wp[1], p2 = wp[2], p3 = wp[3], p4 = wp[4];
        unsigned long long w64[9] = {p0.x, p0.y, p1.x, p1.y, p2.x, p2.y, p3.x, p3.y, p4.x};
        int ps[4] = {0, 0, 0, 0}, pc[4] = {0, 0, 0, 0};
#pragma unroll
        for (int pr = 0; pr < 6; pr++) {
            int i = c_pairI[pr], wr = c_pairW[pr], py = c_pairP[pr];
            uint32_t w0l = (uint32_t)w64[wr * 3],     w0h = (uint32_t)(w64[wr * 3] >> 32);
            uint32_t w1l = (uint32_t)w64[wr * 3 + 1], w1h = (uint32_t)(w64[wr * 3 + 1] >> 32);
            uint32_t w2l = (uint32_t)w64[wr * 3 + 2], w2h = (uint32_t)(w64[wr * 3 + 2] >> 32);
#pragma unroll
            for (int px = 0; px < 2; px++) {
                int k = i * 4 + px;
                uint32_t a0 = lop3_xm(wl[k],     w0l, msk[k]);
                uint32_t a1 = lop3_xm(wl[k + 1], w1l, msk[k + 1]);
                uint32_t a2 = lop3_xm(wl[k + 2], w2l, msk[k + 2]);
                uint32_t b0 = lop3_xm(wh[k],     w0h, msk[k]);
                uint32_t b1 = lop3_xm(wh[k + 1], w1h, msk[k + 1]);
                uint32_t b2 = lop3_xm(wh[k + 2], w2h, msk[k + 2]);
                uint32_t sl = lop3_sum(a0, a1, a2), cl = lop3_maj(a0, a1, a2);
                uint32_t sh = lop3_sum(b0, b1, b2), chh = lop3_maj(b0, b1, b2);
                int q = py * 2 + px;
                ps[q] += __popc(sl) + __popc(sh);
                pc[q] += __popc(cl) + __popc(chh);
            }
        }
        int d0 = base[0] - 2 * ps[0] - 4 * pc[0];
        int d1 = base[1] - 2 * ps[1] - 4 * pc[1];
        int d2 = base[2] - 2 * ps[2] - 4 * pc[2];
        int d3 = base[3] - 2 * ps[3] - 4 * pc[3];
        int dmax = max(max(d0, d1), max(d2, d3));
        int dmin = min(min(d0, d1), min(d2, d3));
        float4 bn = sbn[cb + ci];
        int ds = (bn.x >= 0.f) ? dmax : dmin;
        float val = ((float)ds - bn.y) * bn.x + bn.z;
        obits |= (uint32_t)(val >= 0.f) << ci;
    }
    g_h3u[cell * 2 + half] = obits;
}

// ---------------- classifier ----------------
__global__ void __launch_bounds__(256) fc_kernel(const float* __restrict__ w_head,
                                                 const float* __restrict__ b_head,
                                                 float* __restrict__ out) {
    __shared__ unsigned long long xrow[49];
    __shared__ float h4[256];
    int b = blockIdx.x, t = threadIdx.x;
    if (t < 49) {
        uint32_t lo = g_h3u[(b * 49 + t) * 2];
        uint32_t hi = g_h3u[(b * 49 + t) * 2 + 1];
        xrow[t] = (unsigned long long)lo | ((unsigned long long)hi << 32);
    }
    __syncthreads();

    const unsigned long long* wr = g_wfcp + t * 49;
    int acc = 0;
#pragma unroll
    for (int p = 0; p < 49; p++) acc += __popcll(xrow[p] ^ wr[p]);
    float4 bn = g_bn4[t];
    h4[t] = ((float)(3136 - 2 * acc) - bn.y) * bn.x + bn.z;
    __syncthreads();

    if (t < 10) {
        float s = b_head[t];
        const float* wh = w_head + t * 256;
#pragma unroll 8
        for (int c = 0; c < 256; c++) s += h4[c] * wh[c];
        out[b * 10 + t] = s;
    }
}

// ---------------- launch ----------------
extern "C" void kernel_launch(void* const* d_in, const int* in_sizes, int n_in,
                              void* d_out, int out_size) {
    const float* x      = (const float*)d_in[0];
    const float* w_stem = (const float*)d_in[1];
    const float* g1 = (const float*)d_in[2];
    const float* b1 = (const float*)d_in[3];
    const float* m1 = (const float*)d_in[4];
    const float* v1 = (const float*)d_in[5];
    const float* w2 = (const float*)d_in[6];
    const float* g2 = (const float*)d_in[7];
    const float* b2 = (const float*)d_in[8];
    const float* m2 = (const float*)d_in[9];
    const float* v2 = (const float*)d_in[10];
    const float* w3 = (const float*)d_in[11];
    const float* g3 = (const float*)d_in[12];
    const float* b3 = (const float*)d_in[13];
    const float* m3 = (const float*)d_in[14];
    const float* v3 = (const float*)d_in[15];
    const float* w_fc = (const float*)d_in[16];
    const float* g4 = (const float*)d_in[17];
    const float* b4 = (const float*)d_in[18];
    const float* m4 = (const float*)d_in[19];
    const float* v4 = (const float*)d_in[20];
    const float* w_head = (const float*)d_in[21];
    const float* b_head = (const float*)d_in[22];
    float* out = (float*)d_out;

    pack_kernel<<<57, 256>>>(w2, w3, w_fc, g1, v1, m1, b1, g2, v2, m2, b2,
                             g3, v3, m3, b3, g4, v4, m4, b4);
    stem_kernel<<<(BATCH * 784 * 2) / 256, 256>>>(x, w_stem);
    conv2_kernel<<<(BATCH * 196 * 2) / 256, 256>>>();
    conv3_kernel<<<(BATCH * 49 * 2) / 256, 256>>>();
    fc_kernel<<<BATCH, 256>>>(w_head, b_head, out);
}

// round 6
// speedup vs baseline: 1.8400x; 1.8400x over previous
#include <cuda_runtime.h>
#include <stdint.h>

#define BATCH 2048
#define EPS 1e-5f

// ---------------- static scratch ----------------
__device__ uint32_t           g_h1[BATCH * 784];        // stem out, 32 ch packed
__device__ unsigned long long g_h2[BATCH * 196];        // block1 out, 64 ch packed (u16 quarters)
__device__ uint32_t           g_h3u[BATCH * 49 * 2];    // block2 out (u16 quarters)
__device__ uint32_t           g_w2p[64 * 12];           // sign(w2), stride 12 (uint4)
__device__ unsigned long long g_w3p[64 * 10];           // sign(w3), stride 10 (ulonglong2)
__device__ unsigned long long g_wfcp[256 * 49];         // sign(w_fc)
__device__ float4 g_bn1[32], g_bn2[64], g_bn3[64], g_bn4[256];  // (inv, mean, beta, 0)

// ---------------- packing + BN precompute ----------------
__global__ void pack_kernel(const float* __restrict__ w2, const float* __restrict__ w3,
                            const float* __restrict__ wfc,
                            const float* __restrict__ g1, const float* __restrict__ v1,
                            const float* __restrict__ m1, const float* __restrict__ b1,
                            const float* __restrict__ g2, const float* __restrict__ v2,
                            const float* __restrict__ m2, const float* __restrict__ b2,
                            const float* __restrict__ g3, const float* __restrict__ v3,
                            const float* __restrict__ m3, const float* __restrict__ b3,
                            const float* __restrict__ g4, const float* __restrict__ v4,
                            const float* __restrict__ m4, const float* __restrict__ b4) {
    int idx = blockIdx.x * 256 + threadIdx.x;
    if (idx < 768) {                                   // w2: [64,32,3,3] -> stride 12
        int o = idx / 12, t = idx % 12;
        uint32_t bits = 0;
        if (t < 9)
            for (int c = 0; c < 32; c++)
                bits |= (w2[o * 288 + c * 9 + t] >= 0.f ? 1u : 0u) << c;
        g_w2p[idx] = bits;
    } else if (idx < 1408) {                           // w3: [64,64,3,3] -> stride 10
        int j = idx - 768; int o = j / 10, t = j % 10;
        unsigned long long bits = 0;
        if (t < 9)
            for (int c = 0; c < 64; c++)
                bits |= (unsigned long long)(w3[o * 576 + c * 9 + t] >= 0.f) << c;
        g_w3p[j] = bits;
    } else if (idx < 13952) {                          // w_fc: [256,3136]
        int j = idx - 1408; int o = j / 49, p = j % 49;
        unsigned long long bits = 0;
        for (int c = 0; c < 64; c++)
            bits |= (unsigned long long)(wfc[o * 3136 + c * 49 + p] >= 0.f) << c;
        g_wfcp[j] = bits;
    } else if (idx < 13984) {
        int c = idx - 13952;
        g_bn1[c] = make_float4(g1[c] / sqrtf(v1[c] + EPS), m1[c], b1[c], 0.f);
    } else if (idx < 14048) {
        int c = idx - 13984;
        g_bn2[c] = make_float4(g2[c] / sqrtf(v2[c] + EPS), m2[c], b2[c], 0.f);
    } else if (idx < 14112) {
        int c = idx - 14048;
        g_bn3[c] = make_float4(g3[c] / sqrtf(v3[c] + EPS), m3[c], b3[c], 0.f);
    } else if (idx < 14368) {
        int c = idx - 14112;
        g_bn4[c] = make_float4(g4[c] / sqrtf(v4[c] + EPS), m4[c], b4[c], 0.f);
    }
}

// ---------------- stem: fp32 conv3x3(1->32) + BN + sign, 16 ch/thread ----------------
__global__ void __launch_bounds__(256) stem_kernel(const float* __restrict__ x,
                                                   const float* __restrict__ ws) {
    __shared__ float sw[288];
    __shared__ float4 sbn[32];
    int t = threadIdx.x;
    for (int i = t; i < 288; i += 256) sw[i] = ws[i];
    if (t < 32) sbn[t] = g_bn1[t];
    __syncthreads();

    int idx = blockIdx.x * 256 + t;
    int pix = idx >> 1, half = idx & 1;
    int b = pix / 784, p = pix % 784;
    int y = p / 28, xx = p % 28;
    const float* xb = x + b * 784;

    float win[9];
#pragma unroll
    for (int dy = 0; dy < 3; dy++)
#pragma unroll
        for (int dx = 0; dx < 3; dx++) {
            int yy = y + dy - 1, xc = xx + dx - 1;
            win[dy * 3 + dx] = (yy >= 0 && yy < 28 && xc >= 0 && xc < 28) ? xb[yy * 28 + xc] : 0.f;
        }

    int cb = half * 16;
    uint32_t bits = 0;
#pragma unroll
    for (int ci = 0; ci < 16; ci++) {
        int c = cb + ci;
        float s = 0.f;
#pragma unroll
        for (int k = 0; k < 9; k++) s += sw[c * 9 + k] * win[k];
        float4 bn = sbn[c];
        float v = (s - bn.y) * bn.x + bn.z;
        bits |= (v >= 0.f ? 1u : 0u) << ci;
    }
    ((uint16_t*)g_h1)[pix * 2 + half] = (uint16_t)bits;
}

// ---------------- block1: binary conv(32->64) + BN + pool + sign, 16 ch/thread ----------------
__global__ void __launch_bounds__(256) conv2_kernel() {
    __shared__ __align__(16) uint32_t swt[768];
    __shared__ float4 sbn[64];
    int t = threadIdx.x;
    for (int i = t; i < 768; i += 256) swt[i] = g_w2p[i];
    if (t < 64) sbn[t] = g_bn2[t];
    __syncthreads();

    int idx = blockIdx.x * 256 + t;                 // 2048*196*4 threads
    int cell = idx >> 2, q = idx & 3;
    int b = cell / 196, p = cell % 196;
    int oy = p / 14, ox = p % 14;
    const uint32_t* h = g_h1 + b * 784;

    int rbase = 2 * oy - 1, cbase = 2 * ox - 1;
    bool rv0 = oy > 0, rv3 = oy < 13, cv0 = ox > 0, cv3 = ox < 13;

    uint32_t win[16], msk[16];
#pragma unroll
    for (int i = 0; i < 4; i++) {
        bool rok = (i == 0) ? rv0 : (i == 3 ? rv3 : true);
#pragma unroll
        for (int j = 0; j < 4; j++) {
            bool cok = (j == 0) ? cv0 : (j == 3 ? cv3 : true);
            bool v = rok && cok;
            msk[i * 4 + j] = v ? 0xFFFFFFFFu : 0u;
            win[i * 4 + j] = v ? h[(rbase + i) * 28 + (cbase + j)] : 0u;
        }
    }
    int vr0 = rv0 ? 3 : 2, vr1 = rv3 ? 3 : 2;
    int vc0 = cv0 ? 3 : 2, vc1 = cv3 ? 3 : 2;
    int base0 = 32 * vr0 * vc0, base1 = 32 * vr0 * vc1;
    int base2 = 32 * vr1 * vc0, base3 = 32 * vr1 * vc1;

    int cb = q * 16;
    uint32_t obits = 0;
#pragma unroll 2
    for (int ci = 0; ci < 16; ci++) {
        const uint4* wp = (const uint4*)(swt + (cb + ci) * 12);
        uint4 wa = wp[0], wb = wp[1], wc = wp[2];
        uint32_t wt[9] = {wa.x, wa.y, wa.z, wa.w, wb.x, wb.y, wb.z, wb.w, wc.x};
        int a0 = 0, a1 = 0, a2 = 0, a3 = 0;
#pragma unroll
        for (int dy = 0; dy < 3; dy++)
#pragma unroll
            for (int dx = 0; dx < 3; dx++) {
                uint32_t w = wt[dy * 3 + dx];
                int i0 = dy * 4 + dx;
                a0 += __popc((win[i0] ^ w) & msk[i0]);
                a1 += __popc((win[i0 + 1] ^ w) & msk[i0 + 1]);
                a2 += __popc((win[i0 + 4] ^ w) & msk[i0 + 4]);
                a3 += __popc((win[i0 + 5] ^ w) & msk[i0 + 5]);
            }
        int d0 = base0 - 2 * a0, d1 = base1 - 2 * a1;
        int d2 = base2 - 2 * a2, d3 = base3 - 2 * a3;
        int dmax = max(max(d0, d1), max(d2, d3));
        int dmin = min(min(d0, d1), min(d2, d3));
        float4 bn = sbn[cb + ci];
        int ds = (bn.x >= 0.f) ? dmax : dmin;       // BN monotone in dot -> exact
        float val = ((float)ds - bn.y) * bn.x + bn.z;
        obits |= (uint32_t)(val >= 0.f) << ci;
    }
    ((uint16_t*)g_h2)[cell * 4 + q] = (uint16_t)obits;
}

// ---------------- block2: binary conv(64->64) + BN + pool + sign, 16 ch/thread ----------------
__global__ void __launch_bounds__(256) conv3_kernel() {
    __shared__ __align__(16) unsigned long long swt[640];
    __shared__ float4 sbn[64];
    int t = threadIdx.x;
    for (int i = t; i < 640; i += 256) swt[i] = g_w3p[i];
    if (t < 64) sbn[t] = g_bn3[t];
    __syncthreads();

    int idx = blockIdx.x * 256 + t;                 // 2048*49*4 threads
    int cell = idx >> 2, q = idx & 3;
    int b = cell / 49, p = cell % 49;
    int oy = p / 7, ox = p % 7;
    const unsigned long long* h = g_h2 + b * 196;

    int rbase = 2 * oy - 1, cbase = 2 * ox - 1;
    bool rv0 = oy > 0, rv3 = oy < 6, cv0 = ox > 0, cv3 = ox < 6;

    unsigned long long win[16], msk[16];
#pragma unroll
    for (int i = 0; i < 4; i++) {
        bool rok = (i == 0) ? rv0 : (i == 3 ? rv3 : true);
#pragma unroll
        for (int j = 0; j < 4; j++) {
            bool cok = (j == 0) ? cv0 : (j == 3 ? cv3 : true);
            bool v = rok && cok;
            msk[i * 4 + j] = v ? ~0ull : 0ull;
            win[i * 4 + j] = v ? h[(rbase + i) * 14 + (cbase + j)] : 0ull;
        }
    }
    int vr0 = rv0 ? 3 : 2, vr1 = rv3 ? 3 : 2;
    int vc0 = cv0 ? 3 : 2, vc1 = cv3 ? 3 : 2;
    int base0 = 64 * vr0 * vc0, base1 = 64 * vr0 * vc1;
    int base2 = 64 * vr1 * vc0, base3 = 64 * vr1 * vc1;

    int cb = q * 16;
    uint32_t obits = 0;
#pragma unroll 2
    for (int ci = 0; ci < 16; ci++) {
        const ulonglong2* wp = (const ulonglong2*)(swt + (cb + ci) * 10);
        ulonglong2 p0 = wp[0], p1 = wp[1], p2 = wp[2], p3 = wp[3], p4 = wp[4];
        unsigned long long wt[9] = {p0.x, p0.y, p1.x, p1.y, p2.x, p2.y, p3.x, p3.y, p4.x};
        int a0 = 0, a1 = 0, a2 = 0, a3 = 0;
#pragma unroll
        for (int dy = 0; dy < 3; dy++)
#pragma unroll
            for (int dx = 0; dx < 3; dx++) {
                unsigned long long w = wt[dy * 3 + dx];
                int i0 = dy * 4 + dx;
                a0 += __popcll((win[i0] ^ w) & msk[i0]);
                a1 += __popcll((win[i0 + 1] ^ w) & msk[i0 + 1]);
                a2 += __popcll((win[i0 + 4] ^ w) & msk[i0 + 4]);
                a3 += __popcll((win[i0 + 5] ^ w) & msk[i0 + 5]);
            }
        int d0 = base0 - 2 * a0, d1 = base1 - 2 * a1;
        int d2 = base2 - 2 * a2, d3 = base3 - 2 * a3;
        int dmax = max(max(d0, d1), max(d2, d3));
        int dmin = min(min(d0, d1), min(d2, d3));
        float4 bn = sbn[cb + ci];
        int ds = (bn.x >= 0.f) ? dmax : dmin;
        float val = ((float)ds - bn.y) * bn.x + bn.z;
        obits |= (uint32_t)(val >= 0.f) << ci;
    }
    ((uint16_t*)g_h3u)[cell * 4 + q] = (uint16_t)obits;
}

// ---------------- classifier ----------------
__global__ void __launch_bounds__(256) fc_kernel(const float* __restrict__ w_head,
                                                 const float* __restrict__ b_head,
                                                 float* __restrict__ out) {
    __shared__ unsigned long long xrow[49];
    __shared__ float h4[256];
    int b = blockIdx.x, t = threadIdx.x;
    if (t < 49) {
        uint32_t lo = g_h3u[(b * 49 + t) * 2];
        uint32_t hi = g_h3u[(b * 49 + t) * 2 + 1];
        xrow[t] = (unsigned long long)lo | ((unsigned long long)hi << 32);
    }
    __syncthreads();

    const unsigned long long* wr = g_wfcp + t * 49;
    int acc = 0;
#pragma unroll
    for (int p = 0; p < 49; p++) acc += __popcll(xrow[p] ^ wr[p]);
    float4 bn = g_bn4[t];
    h4[t] = ((float)(3136 - 2 * acc) - bn.y) * bn.x + bn.z;
    __syncthreads();

    if (t < 10) {
        float s = b_head[t];
        const float* wh = w_head + t * 256;
#pragma unroll 8
        for (int c = 0; c < 256; c++) s += h4[c] * wh[c];
        out[b * 10 + t] = s;
    }
}

// ---------------- launch ----------------
extern "C" void kernel_launch(void* const* d_in, const int* in_sizes, int n_in,
                              void* d_out, int out_size) {
    const float* x      = (const float*)d_in[0];
    const float* w_stem = (const float*)d_in[1];
    const float* g1 = (const float*)d_in[2];
    const float* b1 = (const float*)d_in[3];
    const float* m1 = (const float*)d_in[4];
    const float* v1 = (const float*)d_in[5];
    const float* w2 = (const float*)d_in[6];
    const float* g2 = (const float*)d_in[7];
    const float* b2 = (const float*)d_in[8];
    const float* m2 = (const float*)d_in[9];
    const float* v2 = (const float*)d_in[10];
    const float* w3 = (const float*)d_in[11];
    const float* g3 = (const float*)d_in[12];
    const float* b3 = (const float*)d_in[13];
    const float* m3 = (const float*)d_in[14];
    const float* v3 = (const float*)d_in[15];
    const float* w_fc = (const float*)d_in[16];
    const float* g4 = (const float*)d_in[17];
    const float* b4 = (const float*)d_in[18];
    const float* m4 = (const float*)d_in[19];
    const float* v4 = (const float*)d_in[20];
    const float* w_head = (const float*)d_in[21];
    const float* b_head = (const float*)d_in[22];
    float* out = (float*)d_out;

    pack_kernel<<<57, 256>>>(w2, w3, w_fc, g1, v1, m1, b1, g2, v2, m2, b2,
                             g3, v3, m3, b3, g4, v4, m4, b4);
    stem_kernel<<<(BATCH * 784 * 2) / 256, 256>>>(x, w_stem);
    conv2_kernel<<<(BATCH * 196 * 4) / 256, 256>>>();
    conv3_kernel<<<(BATCH * 49 * 4) / 256, 256>>>();
    fc_kernel<<<BATCH, 256>>>(w_head, b_head, out);
}

// round 8
// speedup vs baseline: 1.9697x; 1.0705x over previous
#include <cuda_runtime.h>
#include <stdint.h>

#define BATCH 2048
#define EPS 1e-5f

// ---------------- static scratch ----------------
__device__ uint32_t           g_h1[BATCH * 784];        // stem out, 32 ch packed
__device__ unsigned long long g_h2[BATCH * 196];        // block1 out, 64 ch packed (u32 halves)
__device__ uint32_t           g_h3u[BATCH * 49 * 2];    // block2 out, u32 halves
__device__ uint32_t           g_w2p[64 * 12];           // sign(w2), [ch][tap] stride 12
__device__ unsigned long long g_w3p[64 * 10];           // sign(w3), [ch][tap] stride 10
__device__ unsigned long long g_wfcp[256 * 49];         // sign(w_fc)
__device__ float4 g_bn1[32], g_bn4[256];                // (inv, mean, beta, 0)
__device__ int2   g_th2[64], g_th3[64];                 // (integer threshold, sgn)

// ---------------- packing + BN + integer thresholds ----------------
__global__ void pack_kernel(const float* __restrict__ w2, const float* __restrict__ w3,
                            const float* __restrict__ wfc,
                            const float* __restrict__ g1, const float* __restrict__ v1,
                            const float* __restrict__ m1, const float* __restrict__ b1,
                            const float* __restrict__ g2, const float* __restrict__ v2,
                            const float* __restrict__ m2, const float* __restrict__ b2,
                            const float* __restrict__ g3, const float* __restrict__ v3,
                            const float* __restrict__ m3, const float* __restrict__ b3,
                            const float* __restrict__ g4, const float* __restrict__ v4,
                            const float* __restrict__ m4, const float* __restrict__ b4) {
    int idx = blockIdx.x * 256 + threadIdx.x;
    if (idx < 768) {                                   // w2: [64,32,3,3] -> stride 12
        int o = idx / 12, t = idx % 12;
        uint32_t bits = 0;
        if (t < 9)
            for (int c = 0; c < 32; c++)
                bits |= (w2[o * 288 + c * 9 + t] >= 0.f ? 1u : 0u) << c;
        g_w2p[idx] = bits;
    } else if (idx < 1408) {                           // w3: [64,64,3,3] -> stride 10
        int j = idx - 768; int o = j / 10, t = j % 10;
        unsigned long long bits = 0;
        if (t < 9)
            for (int c = 0; c < 64; c++)
                bits |= (unsigned long long)(w3[o * 576 + c * 9 + t] >= 0.f) << c;
        g_w3p[j] = bits;
    } else if (idx < 13952) {                          // w_fc: [256,3136]
        int j = idx - 1408; int o = j / 49, p = j % 49;
        unsigned long long bits = 0;
        for (int c = 0; c < 64; c++)
            bits |= (unsigned long long)(wfc[o * 3136 + c * 49 + p] >= 0.f) << c;
        g_wfcp[j] = bits;
    } else if (idx < 13984) {
        int c = idx - 13952;
        g_bn1[c] = make_float4(g1[c] / sqrtf(v1[c] + EPS), m1[c], b1[c], 0.f);
    } else if (idx < 14240) {
        int c = idx - 13984;
        g_bn4[c] = make_float4(g4[c] / sqrtf(v4[c] + EPS), m4[c], b4[c], 0.f);
    } else if (idx < 14304) {                          // conv2 thresholds (d in [-288,288], even)
        int c = idx - 14240;
        float inv = g2[c] / sqrtf(v2[c] + EPS), m = m2[c], be = b2[c];
        int sgn = (inv >= 0.f) ? 1 : 0;
        int T;
        if (sgn) {
            T = 10000;
            for (int d = -288; d <= 288; d += 2)
                if (((float)d - m) * inv + be >= 0.f) { T = d; break; }
        } else {
            T = -10000;
            for (int d = 288; d >= -288; d -= 2)
                if (((float)d - m) * inv + be >= 0.f) { T = d; break; }
        }
        g_th2[c] = make_int2(T, sgn);
    } else if (idx < 14368) {                          // conv3 thresholds (d in [-576,576], even)
        int c = idx - 14304;
        float inv = g3[c] / sqrtf(v3[c] + EPS), m = m3[c], be = b3[c];
        int sgn = (inv >= 0.f) ? 1 : 0;
        int T;
        if (sgn) {
            T = 10000;
            for (int d = -576; d <= 576; d += 2)
                if (((float)d - m) * inv + be >= 0.f) { T = d; break; }
        } else {
            T = -10000;
            for (int d = 576; d >= -576; d -= 2)
                if (((float)d - m) * inv + be >= 0.f) { T = d; break; }
        }
        g_th3[c] = make_int2(T, sgn);
    }
}

// ---------------- stem: fp32 conv3x3(1->32) + BN + sign, 16 ch/thread ----------------
__global__ void __launch_bounds__(256) stem_kernel(const float* __restrict__ x,
                                                   const float* __restrict__ ws) {
    __shared__ float sw[288];
    __shared__ float4 sbn[32];
    int t = threadIdx.x;
    for (int i = t; i < 288; i += 256) sw[i] = ws[i];
    if (t < 32) sbn[t] = g_bn1[t];
    __syncthreads();

    int idx = blockIdx.x * 256 + t;
    int pix = idx >> 1, half = idx & 1;
    int b = pix / 784, p = pix % 784;
    int y = p / 28, xx = p % 28;
    const float* xb = x + b * 784;

    float win[9];
#pragma unroll
    for (int dy = 0; dy < 3; dy++)
#pragma unroll
        for (int dx = 0; dx < 3; dx++) {
            int yy = y + dy - 1, xc = xx + dx - 1;
            win[dy * 3 + dx] = (yy >= 0 && yy < 28 && xc >= 0 && xc < 28) ? xb[yy * 28 + xc] : 0.f;
        }

    int cb = half * 16;
    uint32_t bits = 0;
#pragma unroll
    for (int ci = 0; ci < 16; ci++) {
        int c = cb + ci;
        float s = 0.f;
#pragma unroll
        for (int k = 0; k < 9; k++) s += sw[c * 9 + k] * win[k];
        float4 bn = sbn[c];
        float v = (s - bn.y) * bn.x + bn.z;
        bits |= (v >= 0.f ? 1u : 0u) << ci;
    }
    ((uint16_t*)g_h1)[pix * 2 + half] = (uint16_t)bits;
}

// ---------------- block1: warp per (image, pooled row, ch-half), lane = channel ----------------
__global__ void __launch_bounds__(256) conv2_kernel() {
    __shared__ uint32_t stile[4][4][28];               // 4 units x 4 input rows x 28 cols
    int tid = threadIdx.x;
    int U0 = blockIdx.x * 4;
    for (int i = tid; i < 448; i += 256) {
        int u = i / 112, r = i % 112, j = r / 28, col = r % 28;
        int U = U0 + u, b = U / 14, oy = U % 14;
        int ir = 2 * oy - 1 + j;
        stile[u][j][col] = (ir >= 0 && ir < 28) ? g_h1[b * 784 + ir * 28 + col] : 0u;
    }
    __syncthreads();

    int w = tid >> 5, lane = tid & 31;
    int u = w >> 1, h = w & 1;
    int U = U0 + u, b = U / 14, oy = U % 14;
    int c = h * 32 + lane;

    uint32_t wt[9];
#pragma unroll
    for (int t = 0; t < 9; t++) wt[t] = g_w2p[c * 12 + t];
    int pw[9];
#pragma unroll
    for (int t = 0; t < 9; t++) pw[t] = __popc(wt[t]);

    bool e0 = (oy == 0), e1 = (oy == 13);              // r0 top row missing / r1 bottom missing
    int v0 = e0 ? 2 : 3, v1 = e1 ? 2 : 3;
    int Ci0 = 96 * v0 + (e0 ? 2 * (pw[0] + pw[1] + pw[2]) : 0);
    int Ci1 = 96 * v1 + (e1 ? 2 * (pw[6] + pw[7] + pw[8]) : 0);
    int Cl0 = 64 * v0 + (e0 ? 2 * (pw[1] + pw[2]) : 0);   // X=0 edge (dx in {1,2})
    int Cl1 = 64 * v1 + (e1 ? 2 * (pw[7] + pw[8]) : 0);
    int Cr0 = 64 * v0 + (e0 ? 2 * (pw[0] + pw[1]) : 0);   // X=27 edge (dx in {0,1})
    int Cr1 = 64 * v1 + (e1 ? 2 * (pw[6] + pw[7]) : 0);

    int2 th = g_th2[c];
    int T = th.x;
    bool sgn = th.y != 0;
    const uint32_t* tr = &stile[u][0][0];
    uint32_t* outp = ((uint32_t*)g_h2) + (b * 196 + oy * 14) * 2 + h;

#define C2_INT(X, nb) { \
    int a0 = 0, a1 = 0; \
    _Pragma("unroll") \
    for (int dy = 0; dy < 3; dy++) { \
        a0 += __popc(tr[dy*28+(X)-1] ^ wt[3*dy]) + __popc(tr[dy*28+(X)] ^ wt[3*dy+1]) \
            + __popc(tr[dy*28+(X)+1] ^ wt[3*dy+2]); \
        a1 += __popc(tr[(dy+1)*28+(X)-1] ^ wt[3*dy]) + __popc(tr[(dy+1)*28+(X)] ^ wt[3*dy+1]) \
            + __popc(tr[(dy+1)*28+(X)+1] ^ wt[3*dy+2]); \
    } \
    int d0 = Ci0 - 2 * a0, d1 = Ci1 - 2 * a1; \
    nb = sgn ? (max(d0, d1) >= T) : (min(d0, d1) <= T); }

    bool nb0, nb1;
    {   // X = 0 edge: taps dx in {1,2} read cols 0,1
        int a0 = 0, a1 = 0;
#pragma unroll
        for (int dy = 0; dy < 3; dy++) {
            a0 += __popc(tr[dy * 28 + 0] ^ wt[3 * dy + 1]) + __popc(tr[dy * 28 + 1] ^ wt[3 * dy + 2]);
            a1 += __popc(tr[(dy + 1) * 28 + 0] ^ wt[3 * dy + 1]) + __popc(tr[(dy + 1) * 28 + 1] ^ wt[3 * dy + 2]);
        }
        int d0 = Cl0 - 2 * a0, d1 = Cl1 - 2 * a1;
        nb0 = sgn ? (max(d0, d1) >= T) : (min(d0, d1) <= T);
    }
    C2_INT(1, nb1);
    uint32_t bal = __ballot_sync(0xffffffffu, nb0 | nb1);
    if (lane == 0) outp[0] = bal;

#pragma unroll 2
    for (int ox = 1; ox <= 12; ox++) {
        C2_INT(2 * ox, nb0);
        C2_INT(2 * ox + 1, nb1);
        bal = __ballot_sync(0xffffffffu, nb0 | nb1);
        if (lane == 0) outp[ox * 2] = bal;
    }

    C2_INT(26, nb0);
    {   // X = 27 edge: taps dx in {0,1} read cols 26,27
        int a0 = 0, a1 = 0;
#pragma unroll
        for (int dy = 0; dy < 3; dy++) {
            a0 += __popc(tr[dy * 28 + 26] ^ wt[3 * dy]) + __popc(tr[dy * 28 + 27] ^ wt[3 * dy + 1]);
            a1 += __popc(tr[(dy + 1) * 28 + 26] ^ wt[3 * dy]) + __popc(tr[(dy + 1) * 28 + 27] ^ wt[3 * dy + 1]);
        }
        int d0 = Cr0 - 2 * a0, d1 = Cr1 - 2 * a1;
        nb1 = sgn ? (max(d0, d1) >= T) : (min(d0, d1) <= T);
    }
    bal = __ballot_sync(0xffffffffu, nb0 | nb1);
    if (lane == 0) outp[26] = bal;
#undef C2_INT
}

// ---------------- block2: warp per (image, pooled row, ch-half), lane = channel ----------------
__global__ void __launch_bounds__(256) conv3_kernel() {
    __shared__ unsigned long long stile[4][4][14];     // 4 units x 4 input rows x 14 cols
    int tid = threadIdx.x;
    int U0 = blockIdx.x * 4;
    for (int i = tid; i < 224; i += 256) {
        int u = i / 56, r = i % 56, j = r / 14, col = r % 14;
        int U = U0 + u, b = U / 7, oy = U % 7;
        int ir = 2 * oy - 1 + j;
        stile[u][j][col] = (ir >= 0 && ir < 14) ? g_h2[b * 196 + ir * 14 + col] : 0ull;
    }
    __syncthreads();

    int w = tid >> 5, lane = tid & 31;
    int u = w >> 1, h = w & 1;
    int U = U0 + u, b = U / 7, oy = U % 7;
    int c = h * 32 + lane;

    unsigned long long wt[9];
#pragma unroll
    for (int t = 0; t < 9; t++) wt[t] = g_w3p[c * 10 + t];
    int pw[9];
#pragma unroll
    for (int t = 0; t < 9; t++) pw[t] = __popcll(wt[t]);

    bool e0 = (oy == 0), e1 = (oy == 6);
    int v0 = e0 ? 2 : 3, v1 = e1 ? 2 : 3;
    int Ci0 = 192 * v0 + (e0 ? 2 * (pw[0] + pw[1] + pw[2]) : 0);
    int Ci1 = 192 * v1 + (e1 ? 2 * (pw[6] + pw[7] + pw[8]) : 0);
    int Cl0 = 128 * v0 + (e0 ? 2 * (pw[1] + pw[2]) : 0);
    int Cl1 = 128 * v1 + (e1 ? 2 * (pw[7] + pw[8]) : 0);
    int Cr0 = 128 * v0 + (e0 ? 2 * (pw[0] + pw[1]) : 0);
    int Cr1 = 128 * v1 + (e1 ? 2 * (pw[6] + pw[7]) : 0);

    int2 th = g_th3[c];
    int T = th.x;
    bool sgn = th.y != 0;
    const unsigned long long* tr = &stile[u][0][0];
    uint32_t* outp = g_h3u + (b * 49 + oy * 7) * 2 + h;

#define C3_INT(X, nb) { \
    int a0 = 0, a1 = 0; \
    _Pragma("unroll") \
    for (int dy = 0; dy < 3; dy++) { \
        a0 += __popcll(tr[dy*14+(X)-1] ^ wt[3*dy]) + __popcll(tr[dy*14+(X)] ^ wt[3*dy+1]) \
            + __popcll(tr[dy*14+(X)+1] ^ wt[3*dy+2]); \
        a1 += __popcll(tr[(dy+1)*14+(X)-1] ^ wt[3*dy]) + __popcll(tr[(dy+1)*14+(X)] ^ wt[3*dy+1]) \
            + __popcll(tr[(dy+1)*14+(X)+1] ^ wt[3*dy+2]); \
    } \
    int d0 = Ci0 - 2 * a0, d1 = Ci1 - 2 * a1; \
    nb = sgn ? (max(d0, d1) >= T) : (min(d0, d1) <= T); }

    bool nb0, nb1;
    {   // X = 0 edge
        int a0 = 0, a1 = 0;
#pragma unroll
        for (int dy = 0; dy < 3; dy++) {
            a0 += __popcll(tr[dy * 14 + 0] ^ wt[3 * dy + 1]) + __popcll(tr[dy * 14 + 1] ^ wt[3 * dy + 2]);
            a1 += __popcll(tr[(dy + 1) * 14 + 0] ^ wt[3 * dy + 1]) + __popcll(tr[(dy + 1) * 14 + 1] ^ wt[3 * dy + 2]);
        }
        int d0 = Cl0 - 2 * a0, d1 = Cl1 - 2 * a1;
        nb0 = sgn ? (max(d0, d1) >= T) : (min(d0, d1) <= T);
    }
    C3_INT(1, nb1);
    uint32_t bal = __ballot_sync(0xffffffffu, nb0 | nb1);
    if (lane == 0) outp[0] = bal;

#pragma unroll 2
    for (int ox = 1; ox <= 5; ox++) {
        C3_INT(2 * ox, nb0);
        C3_INT(2 * ox + 1, nb1);
        bal = __ballot_sync(0xffffffffu, nb0 | nb1);
        if (lane == 0) outp[ox * 2] = bal;
    }

    C3_INT(12, nb0);
    {   // X = 13 edge
        int a0 = 0, a1 = 0;
#pragma unroll
        for (int dy = 0; dy < 3; dy++) {
            a0 += __popcll(tr[dy * 14 + 12] ^ wt[3 * dy]) + __popcll(tr[dy * 14 + 13] ^ wt[3 * dy + 1]);
            a1 += __popcll(tr[(dy + 1) * 14 + 12] ^ wt[3 * dy]) + __popcll(tr[(dy + 1) * 14 + 13] ^ wt[3 * dy + 1]);
        }
        int d0 = Cr0 - 2 * a0, d1 = Cr1 - 2 * a1;
        nb1 = sgn ? (max(d0, d1) >= T) : (min(d0, d1) <= T);
    }
    bal = __ballot_sync(0xffffffffu, nb0 | nb1);
    if (lane == 0) outp[12] = bal;
#undef C3_INT
}

// ---------------- classifier ----------------
__global__ void __launch_bounds__(256) fc_kernel(const float* __restrict__ w_head,
                                                 const float* __restrict__ b_head,
                                                 float* __restrict__ out) {
    __shared__ unsigned long long xrow[49];
    __shared__ float h4[256];
    int b = blockIdx.x, t = threadIdx.x;
    if (t < 49) {
        uint32_t lo = g_h3u[(b * 49 + t) * 2];
        uint32_t hi = g_h3u[(b * 49 + t) * 2 + 1];
        xrow[t] = (unsigned long long)lo | ((unsigned long long)hi << 32);
    }
    __syncthreads();

    const unsigned long long* wr = g_wfcp + t * 49;
    int acc = 0;
#pragma unroll
    for (int p = 0; p < 49; p++) acc += __popcll(xrow[p] ^ wr[p]);
    float4 bn = g_bn4[t];
    h4[t] = ((float)(3136 - 2 * acc) - bn.y) * bn.x + bn.z;
    __syncthreads();

    if (t < 10) {
        float s = b_head[t];
        const float* wh = w_head + t * 256;
#pragma unroll 8
        for (int c = 0; c < 256; c++) s += h4[c] * wh[c];
        out[b * 10 + t] = s;
    }
}

// ---------------- launch ----------------
extern "C" void kernel_launch(void* const* d_in, const int* in_sizes, int n_in,
                              void* d_out, int out_size) {
    const float* x      = (const float*)d_in[0];
    const float* w_stem = (const float*)d_in[1];
    const float* g1 = (const float*)d_in[2];
    const float* b1 = (const float*)d_in[3];
    const float* m1 = (const float*)d_in[4];
    const float* v1 = (const float*)d_in[5];
    const float* w2 = (const float*)d_in[6];
    const float* g2 = (const float*)d_in[7];
    const float* b2 = (const float*)d_in[8];
    const float* m2 = (const float*)d_in[9];
    const float* v2 = (const float*)d_in[10];
    const float* w3 = (const float*)d_in[11];
    const float* g3 = (const float*)d_in[12];
    const float* b3 = (const float*)d_in[13];
    const float* m3 = (const float*)d_in[14];
    const float* v3 = (const float*)d_in[15];
    const float* w_fc = (const float*)d_in[16];
    const float* g4 = (const float*)d_in[17];
    const float* b4 = (const float*)d_in[18];
    const float* m4 = (const float*)d_in[19];
    const float* v4 = (const float*)d_in[20];
    const float* w_head = (const float*)d_in[21];
    const float* b_head = (const float*)d_in[22];
    float* out = (float*)d_out;

    pack_kernel<<<57, 256>>>(w2, w3, w_fc, g1, v1, m1, b1, g2, v2, m2, b2,
                             g3, v3, m3, b3, g4, v4, m4, b4);
    stem_kernel<<<(BATCH * 784 * 2) / 256, 256>>>(x, w_stem);
    conv2_kernel<<<(BATCH * 14) / 4, 256>>>();   // 7168 blocks: 4 (img,row) units x 2 halves
    conv3_kernel<<<(BATCH * 7) / 4, 256>>>();    // 3584 blocks
    fc_kernel<<<BATCH, 256>>>(w_head, b_head, out);
}